// round 2
// baseline (speedup 1.0000x reference)
#include <cuda_runtime.h>
#include <math.h>
#include <stdint.h>

// Problem constants
#define NUM_CODES 4096
#define D 64
#define NB 8
#define HW 4096            // 64*64
#define N_VEC 32768        // NB*HW
#define ZQ_ELEMS 2097152   // N_VEC * D

// Output layout (flattened tuple, fp32): z_q, loss, perplexity, encodings, indices
#define OFF_ZQ   0
#define OFF_LOSS 2097152
#define OFF_PERP 2097153
#define OFF_ENC  2097154ULL
#define ENC_ELEMS 134217728ULL           // N_VEC * NUM_CODES
#define OFF_IND  (OFF_ENC + ENC_ELEMS)   // 136314882
#define OUT_FULL (OFF_IND + N_VEC)       // 136347650

#define BETA 0.25f

// Scratch (device globals; no allocation allowed)
__device__ float g_wsq[NUM_CODES];
__device__ int   g_idx[N_VEC];
__device__ int   g_counts[NUM_CODES];
__device__ float g_loss;

// ---------------------------------------------------------------------------
// 0.5*||w_k||^2 per code (one warp per code, coalesced)
// ---------------------------------------------------------------------------
__global__ void wsq_kernel(const float* __restrict__ w) {
    int gwarp = (blockIdx.x * blockDim.x + threadIdx.x) >> 5;
    int lane = threadIdx.x & 31;
    if (gwarp >= NUM_CODES) return;
    const float* row = w + gwarp * D;
    float s = 0.f;
    #pragma unroll
    for (int j = 0; j < D; j += 32) {
        float v = row[j + lane];
        s += v * v;
    }
    #pragma unroll
    for (int o = 16; o; o >>= 1) s += __shfl_xor_sync(0xffffffffu, s, o);
    if (lane == 0) g_wsq[gwarp] = 0.5f * s;
}

__global__ void init_kernel() {
    int t = blockIdx.x * blockDim.x + threadIdx.x;
    if (t < NUM_CODES) g_counts[t] = 0;
    if (t == 0) g_loss = 0.f;
}

// ---------------------------------------------------------------------------
// Fused GEMM + argmax:
//   score(n,k) = z_n . w_k - 0.5*||w_k||^2   (argmax score == argmin distance)
// Block: 64 z-vectors x all 4096 codes (tiles of 128). 256 threads, 4x8/thread.
// ---------------------------------------------------------------------------
__global__ __launch_bounds__(256) void argmax_kernel(const float* __restrict__ z,
                                                     const float* __restrict__ w) {
    __shared__ float Zs[64 * D];        // 16 KB, row-major [vec][d]
    __shared__ float Ws[128 * D];       // 32 KB, float4-granule XOR swizzled per row

    int tid = threadIdx.x;
    int tx = tid & 15;                  // code dimension (16)
    int ty = tid >> 4;                  // row dimension  (16)

    int nbase = blockIdx.x * 64;
    int b  = nbase >> 12;
    int hw = nbase & 4095;
    const float* zb = z + (size_t)b * 262144 + hw;   // z[b, c, :, :] base + hw

    // Load Z tile: Zs[r*D + c] = z[b, c, hw + r]; coalesced over r.
    for (int e = tid; e < 64 * D; e += 256) {
        int c = e >> 6;
        int r = e & 63;
        Zs[r * D + c] = zb[c * HW + r];
    }

    float bestv[4];
    int   besti[4];
    #pragma unroll
    for (int i = 0; i < 4; i++) { bestv[i] = -3.0e38f; besti[i] = 0; }

    float4* ws4 = (float4*)Ws;
    const float4* zs4 = (const float4*)Zs;

    for (int kb = 0; kb < NUM_CODES; kb += 128) {
        // Load W tile (128 codes x 64 floats) with XOR swizzle on float4 granule
        const float4* wg = (const float4*)(w + (size_t)kb * D);
        for (int e = tid; e < 128 * 16; e += 256) {
            int c = e >> 4;
            int g = e & 15;
            ws4[c * 16 + (g ^ (c & 7))] = wg[c * 16 + g];
        }
        __syncthreads();

        float acc[4][8];
        #pragma unroll
        for (int i = 0; i < 4; i++)
            #pragma unroll
            for (int j = 0; j < 8; j++) acc[i][j] = 0.f;

        #pragma unroll
        for (int kk = 0; kk < 16; kk++) {
            float4 a[4], bb[8];
            #pragma unroll
            for (int i = 0; i < 4; i++) a[i] = zs4[(ty + 16 * i) * 16 + kk];
            #pragma unroll
            for (int j = 0; j < 8; j++) {
                int c = tx + 16 * j;
                bb[j] = ws4[c * 16 + (kk ^ (c & 7))];
            }
            #pragma unroll
            for (int i = 0; i < 4; i++)
                #pragma unroll
                for (int j = 0; j < 8; j++)
                    acc[i][j] += a[i].x * bb[j].x + a[i].y * bb[j].y +
                                 a[i].z * bb[j].z + a[i].w * bb[j].w;
        }

        // Per-tile best update (codes ascend with kb and j -> first-min kept)
        #pragma unroll
        for (int j = 0; j < 8; j++) {
            int c = tx + 16 * j;
            float q = g_wsq[kb + c];
            #pragma unroll
            for (int i = 0; i < 4; i++) {
                float s = acc[i][j] - q;
                if (s > bestv[i]) { bestv[i] = s; besti[i] = kb + c; }
            }
        }
        __syncthreads();
    }

    // Reduce across the 16 tx lanes (contiguous half-warp segments, width=16).
    #pragma unroll
    for (int i = 0; i < 4; i++) {
        float v = bestv[i];
        int ix = besti[i];
        #pragma unroll
        for (int o = 8; o; o >>= 1) {
            float ov = __shfl_down_sync(0xffffffffu, v, o, 16);
            int   oi = __shfl_down_sync(0xffffffffu, ix, o, 16);
            if (ov > v || (ov == v && oi < ix)) { v = ov; ix = oi; }
        }
        if (tx == 0) g_idx[nbase + ty + 16 * i] = ix;
    }
}

// ---------------------------------------------------------------------------
// Pass 2: z_q gather (transposed), loss accum, one-hot scatter, indices, hist.
// One thread per vector n; consecutive lanes = consecutive hw -> coalesced.
// ---------------------------------------------------------------------------
__global__ __launch_bounds__(256) void pass2_kernel(const float* __restrict__ z,
                                                    const float* __restrict__ w,
                                                    float* __restrict__ out) {
    int n = blockIdx.x * 256 + threadIdx.x;
    int idx = g_idx[n];
    int b  = n >> 12;
    int hw = n & 4095;
    const float* zb = z + (size_t)b * 262144 + hw;
    float* zq = out + OFF_ZQ + (size_t)b * 262144 + hw;
    const float* wr = w + (size_t)idx * D;

    float ls = 0.f;
    #pragma unroll 8
    for (int c = 0; c < D; c++) {
        float wv = wr[c];
        float zv = zb[(size_t)c * HW];
        float d = wv - zv;
        ls += d * d;
        zq[(size_t)c * HW] = wv;   // straight-through value == codebook entry
    }

    out[OFF_ENC + (size_t)n * NUM_CODES + (size_t)idx] = 1.0f;
    out[OFF_IND + (size_t)n] = (float)idx;
    atomicAdd(&g_counts[idx], 1);

    __shared__ float red[256];
    red[threadIdx.x] = ls;
    __syncthreads();
    for (int s = 128; s; s >>= 1) {
        if (threadIdx.x < s) red[threadIdx.x] += red[threadIdx.x + s];
        __syncthreads();
    }
    if (threadIdx.x == 0) atomicAdd(&g_loss, red[0]);
}

// z_q-only fallback (in case harness output is just the first tuple element)
__global__ __launch_bounds__(256) void pass2_zq_only(const float* __restrict__ w,
                                                     float* __restrict__ out) {
    int n = blockIdx.x * 256 + threadIdx.x;
    int idx = g_idx[n];
    int b  = n >> 12;
    int hw = n & 4095;
    float* zq = out + (size_t)b * 262144 + hw;
    const float* wr = w + (size_t)idx * D;
    #pragma unroll 8
    for (int c = 0; c < D; c++) zq[(size_t)c * HW] = wr[c];
}

// ---------------------------------------------------------------------------
// Finalize: loss scale + perplexity from histogram
// ---------------------------------------------------------------------------
__global__ void finalize_kernel(float* __restrict__ out) {
    __shared__ float red[256];
    float s = 0.f;
    for (int k = threadIdx.x; k < NUM_CODES; k += 256) {
        float p = (float)g_counts[k] * (1.0f / 32768.0f);
        s += p * logf(p + 1e-10f);
    }
    red[threadIdx.x] = s;
    __syncthreads();
    for (int st = 128; st; st >>= 1) {
        if (threadIdx.x < st) red[threadIdx.x] += red[threadIdx.x + st];
        __syncthreads();
    }
    if (threadIdx.x == 0) {
        out[OFF_PERP] = expf(-red[0]);
        out[OFF_LOSS] = BETA * g_loss * (1.0f / 2097152.0f);
    }
}

// ---------------------------------------------------------------------------
extern "C" void kernel_launch(void* const* d_in, const int* in_sizes, int n_in,
                              void* d_out, int out_size) {
    const float* z = (const float*)d_in[0];
    const float* w = (const float*)d_in[1];
    float* out = (float*)d_out;

    // Distance argmin (shared by both output layouts)
    wsq_kernel<<<512, 256>>>(w);                 // 4096 warps
    init_kernel<<<17, 256>>>();
    argmax_kernel<<<N_VEC / 64, 256>>>(z, w);    // 512 blocks

    if ((unsigned long long)out_size >= OUT_FULL) {
        // Zero the one-hot encodings region (poisoned otherwise)
        cudaMemsetAsync(out + OFF_ENC, 0, ENC_ELEMS * sizeof(float));
        pass2_kernel<<<N_VEC / 256, 256>>>(z, w, out);
        finalize_kernel<<<1, 256>>>(out);
    } else {
        pass2_zq_only<<<N_VEC / 256, 256>>>(w, out);
    }
}